// round 7
// baseline (speedup 1.0000x reference)
#include <cuda_runtime.h>
#include <cuda_bf16.h>
#include <stdint.h>

#define N_NODES  100000
#define N_EDGES  3200000
#define D_IN     256
#define D_OUT    256

// ---------------------------------------------------------------------------
// Device-global scratch
// ---------------------------------------------------------------------------
__device__ float          g_support[(size_t)N_NODES * D_OUT];   // ~102.4 MB
__device__ int            g_row_cnt[N_NODES];
__device__ int            g_row_off[N_NODES + 1];
__device__ int            g_row_cur[N_NODES];
__device__ int            g_csr_col[N_EDGES];
__device__ float          g_csr_val[N_EDGES];
__device__ __nv_bfloat16  g_wt_hi[D_IN * D_OUT];                // transposed [n][k]
__device__ __nv_bfloat16  g_wt_lo[D_IN * D_OUT];
__device__ __nv_bfloat16  g_x_hi[(size_t)N_NODES * D_IN];       // 51.2 MB
__device__ __nv_bfloat16  g_x_lo[(size_t)N_NODES * D_IN];       // 51.2 MB

// ---------------------------------------------------------------------------
// Helpers
// ---------------------------------------------------------------------------
// pack_bf16x2(a, b): lo half = bf16(a), hi half = bf16(b)
__device__ __forceinline__ uint32_t pack_bf16x2(float a, float b) {
    uint32_t r;
    asm("cvt.rn.satfinite.bf16x2.f32 %0, %1, %2;" : "=r"(r) : "f"(b), "f"(a));
    return r;
}

// mma.sync m16n8k16 row.col bf16 -> fp32 accumulate (sm_80+ path, no arch 'a' gate)
__device__ __forceinline__ void mma_bf16(float* c, const uint32_t* a, const uint32_t* b) {
    asm volatile(
        "mma.sync.aligned.m16n8k16.row.col.f32.bf16.bf16.f32 "
        "{%0,%1,%2,%3}, {%4,%5,%6,%7}, {%8,%9}, {%0,%1,%2,%3};"
        : "+f"(c[0]), "+f"(c[1]), "+f"(c[2]), "+f"(c[3])
        : "r"(a[0]), "r"(a[1]), "r"(a[2]), "r"(a[3]), "r"(b[0]), "r"(b[1]));
}

// ---------------------------------------------------------------------------
// 0a) Weight prep: Wt_hi[n][k] = bf16(W[k][n]),  Wt_lo = bf16(residual)
// ---------------------------------------------------------------------------
__global__ void wprep_kernel(const float* __restrict__ W)
{
    const int idx = blockIdx.x * blockDim.x + threadIdx.x;
    if (idx >= D_IN * D_OUT) return;
    const int k = idx / D_OUT;
    const int n = idx % D_OUT;
    const float v = W[idx];
    const __nv_bfloat16 hi = __float2bfloat16_rn(v);
    const float hif = __bfloat162float(hi);
    const __nv_bfloat16 lo = __float2bfloat16_rn(v - hif);
    g_wt_hi[n * D_IN + k] = hi;
    g_wt_lo[n * D_IN + k] = lo;
}

// ---------------------------------------------------------------------------
// 0b) X prep: split fp32 X into bf16 hi/lo (k-contiguous, same layout as X)
// ---------------------------------------------------------------------------
__global__ void xprep_kernel(const float* __restrict__ X)
{
    const int idx = blockIdx.x * blockDim.x + threadIdx.x;   // over M*256/4
    if (idx >= N_NODES * D_IN / 4) return;
    const float4 v = reinterpret_cast<const float4*>(X)[idx];
    const uint32_t hi01 = pack_bf16x2(v.x, v.y);
    const uint32_t hi23 = pack_bf16x2(v.z, v.w);
    const float h0 = __uint_as_float(hi01 << 16);
    const float h1 = __uint_as_float(hi01 & 0xffff0000u);
    const float h2 = __uint_as_float(hi23 << 16);
    const float h3 = __uint_as_float(hi23 & 0xffff0000u);
    const uint32_t lo01 = pack_bf16x2(v.x - h0, v.y - h1);
    const uint32_t lo23 = pack_bf16x2(v.z - h2, v.w - h3);
    reinterpret_cast<uint2*>(g_x_hi)[idx] = make_uint2(hi01, hi23);
    reinterpret_cast<uint2*>(g_x_lo)[idx] = make_uint2(lo01, lo23);
}

// ---------------------------------------------------------------------------
// 1) GEMM: support = x @ W via mma.sync bf16 hi/lo split (3 terms)
//    CTA 128x128, 8 warps in 2(m) x 4(n), warp tile 64x32.
//    All fragments loaded directly from global as b32 (k-contiguous pairs).
// ---------------------------------------------------------------------------
__global__ __launch_bounds__(256, 2)
void gemm_mma_kernel(float* __restrict__ S, int nrows)
{
    const int tid = threadIdx.x;
    const int w   = tid >> 5;
    const int l   = tid & 31;
    const int mblock = blockIdx.y * 128;
    const int nblock = blockIdx.x * 128;       // gridDim.x == 2
    const int wm = (w & 1) * 64;
    const int wn = (w >> 1) * 32;
    const int lr = l >> 2;                     // 0..7
    const int lq = l & 3;                      // k-pair selector

    const uint32_t* __restrict__ Ah = reinterpret_cast<const uint32_t*>(g_x_hi);
    const uint32_t* __restrict__ Al = reinterpret_cast<const uint32_t*>(g_x_lo);
    const uint32_t* __restrict__ Bh = reinterpret_cast<const uint32_t*>(g_wt_hi);
    const uint32_t* __restrict__ Bl = reinterpret_cast<const uint32_t*>(g_wt_lo);
    // b32 row stride = D_IN/2 = 128

    float acc[4][4][4];
    #pragma unroll
    for (int mf = 0; mf < 4; mf++)
        #pragma unroll
        for (int nf = 0; nf < 4; nf++)
            #pragma unroll
            for (int r = 0; r < 4; r++) acc[mf][nf][r] = 0.0f;

    // Row validity (compile-time-ish: only last m-block partial)
    int mrow0[4], mrow1[4];
    bool v0[4], v1[4];
    #pragma unroll
    for (int mf = 0; mf < 4; mf++) {
        mrow0[mf] = mblock + wm + mf * 16 + lr;
        mrow1[mf] = mrow0[mf] + 8;
        v0[mf] = mrow0[mf] < nrows;
        v1[mf] = mrow1[mf] < nrows;
    }

    #pragma unroll 4
    for (int ks = 0; ks < 16; ks++) {
        const int kb = ks * 8 + lq;            // b32 index of k-pair (k0)
        // A fragments: [mf][4] regs; reg layout {m,k0},{m+8,k0},{m,k0+8},{m+8,k0+8}
        uint32_t ah[4][4], al[4][4];
        #pragma unroll
        for (int mf = 0; mf < 4; mf++) {
            const size_t r0 = (size_t)mrow0[mf] * 128;
            const size_t r1 = (size_t)mrow1[mf] * 128;
            ah[mf][0] = v0[mf] ? __ldg(Ah + r0 + kb)     : 0u;
            ah[mf][1] = v1[mf] ? __ldg(Ah + r1 + kb)     : 0u;
            ah[mf][2] = v0[mf] ? __ldg(Ah + r0 + kb + 4) : 0u;
            ah[mf][3] = v1[mf] ? __ldg(Ah + r1 + kb + 4) : 0u;
            al[mf][0] = v0[mf] ? __ldg(Al + r0 + kb)     : 0u;
            al[mf][1] = v1[mf] ? __ldg(Al + r1 + kb)     : 0u;
            al[mf][2] = v0[mf] ? __ldg(Al + r0 + kb + 4) : 0u;
            al[mf][3] = v1[mf] ? __ldg(Al + r1 + kb + 4) : 0u;
        }
        #pragma unroll
        for (int nf = 0; nf < 4; nf++) {
            const int n = nblock + wn + nf * 8 + lr;
            const size_t rb = (size_t)n * 128;
            uint32_t bh[2], bl[2];
            bh[0] = __ldg(Bh + rb + kb);
            bh[1] = __ldg(Bh + rb + kb + 4);
            bl[0] = __ldg(Bl + rb + kb);
            bl[1] = __ldg(Bl + rb + kb + 4);
            #pragma unroll
            for (int mf = 0; mf < 4; mf++) {
                mma_bf16(acc[mf][nf], ah[mf], bh);
                mma_bf16(acc[mf][nf], ah[mf], bl);
                mma_bf16(acc[mf][nf], al[mf], bh);
            }
        }
    }

    // Epilogue: C layout c0,c1 -> (row, col..col+1); c2,c3 -> (row+8, col..col+1)
    #pragma unroll
    for (int mf = 0; mf < 4; mf++) {
        #pragma unroll
        for (int nf = 0; nf < 4; nf++) {
            const int col = nblock + wn + nf * 8 + lq * 2;
            if (v0[mf]) {
                float2* p = reinterpret_cast<float2*>(S + (size_t)mrow0[mf] * D_OUT + col);
                *p = make_float2(acc[mf][nf][0], acc[mf][nf][1]);
            }
            if (v1[mf]) {
                float2* p = reinterpret_cast<float2*>(S + (size_t)mrow1[mf] * D_OUT + col);
                *p = make_float2(acc[mf][nf][2], acc[mf][nf][3]);
            }
        }
    }
}

// ---------------------------------------------------------------------------
// 2) CSR build
// ---------------------------------------------------------------------------
__global__ void zero_counts_kernel()
{
    const int i = blockIdx.x * blockDim.x + threadIdx.x;
    if (i < N_NODES) g_row_cnt[i] = 0;
}

__global__ void count_kernel(const int* __restrict__ erow)
{
    const int e = blockIdx.x * blockDim.x + threadIdx.x;
    if (e < N_EDGES) atomicAdd(&g_row_cnt[erow[e]], 1);
}

__global__ void scan_kernel()
{
    const int T = 1024;
    const int t = threadIdx.x;
    const int chunk = (N_NODES + T - 1) / T;
    const int start = t * chunk;
    const int end   = min(start + chunk, N_NODES);

    int sum = 0;
    for (int i = start; i < end; i++) sum += g_row_cnt[i];

    __shared__ int s[T];
    s[t] = sum;
    __syncthreads();
    for (int d = 1; d < T; d <<= 1) {
        int v = (t >= d) ? s[t - d] : 0;
        __syncthreads();
        s[t] += v;
        __syncthreads();
    }
    int run = s[t] - sum;
    for (int i = start; i < end; i++) {
        const int c = g_row_cnt[i];
        g_row_off[i] = run;
        g_row_cur[i] = run;
        run += c;
    }
    if (end == N_NODES) g_row_off[N_NODES] = run;
}

__global__ void scatter_kernel(const int* __restrict__ erow,
                               const int* __restrict__ ecol,
                               const float* __restrict__ eval)
{
    const int e = blockIdx.x * blockDim.x + threadIdx.x;
    if (e < N_EDGES) {
        const int r   = erow[e];
        const int pos = atomicAdd(&g_row_cur[r], 1);
        g_csr_col[pos] = ecol[e];
        g_csr_val[pos] = eval[e];
    }
}

// ---------------------------------------------------------------------------
// 3) SpMM: warp-per-row, 2-edge software pipeline
// ---------------------------------------------------------------------------
__global__ __launch_bounds__(256)
void spmm_kernel(const float* __restrict__ S, float* __restrict__ out)
{
    const int warp = blockIdx.x * (blockDim.x >> 5) + (threadIdx.x >> 5);
    const int lane = threadIdx.x & 31;
    if (warp >= N_NODES) return;

    const int beg = g_row_off[warp];
    const int end = g_row_off[warp + 1];

    float4 a0 = make_float4(0.f, 0.f, 0.f, 0.f);
    float4 a1 = make_float4(0.f, 0.f, 0.f, 0.f);

    int e = beg;
    for (; e + 2 <= end; e += 2) {
        const int   c0 = __ldg(&g_csr_col[e]);
        const int   c1 = __ldg(&g_csr_col[e + 1]);
        const float v0 = __ldg(&g_csr_val[e]);
        const float v1 = __ldg(&g_csr_val[e + 1]);
        const float4* p0 = reinterpret_cast<const float4*>(S + (size_t)c0 * D_OUT);
        const float4* p1 = reinterpret_cast<const float4*>(S + (size_t)c1 * D_OUT);
        const float4 x0 = __ldg(p0 + lane);
        const float4 x1 = __ldg(p0 + lane + 32);
        const float4 y0 = __ldg(p1 + lane);
        const float4 y1 = __ldg(p1 + lane + 32);
        a0.x = fmaf(v0, x0.x, a0.x); a0.y = fmaf(v0, x0.y, a0.y);
        a0.z = fmaf(v0, x0.z, a0.z); a0.w = fmaf(v0, x0.w, a0.w);
        a1.x = fmaf(v0, x1.x, a1.x); a1.y = fmaf(v0, x1.y, a1.y);
        a1.z = fmaf(v0, x1.z, a1.z); a1.w = fmaf(v0, x1.w, a1.w);
        a0.x = fmaf(v1, y0.x, a0.x); a0.y = fmaf(v1, y0.y, a0.y);
        a0.z = fmaf(v1, y0.z, a0.z); a0.w = fmaf(v1, y0.w, a0.w);
        a1.x = fmaf(v1, y1.x, a1.x); a1.y = fmaf(v1, y1.y, a1.y);
        a1.z = fmaf(v1, y1.z, a1.z); a1.w = fmaf(v1, y1.w, a1.w);
    }
    for (; e < end; e++) {
        const int   c = __ldg(&g_csr_col[e]);
        const float v = __ldg(&g_csr_val[e]);
        const float4* p = reinterpret_cast<const float4*>(S + (size_t)c * D_OUT);
        const float4 s0 = __ldg(p + lane);
        const float4 s1 = __ldg(p + lane + 32);
        a0.x = fmaf(v, s0.x, a0.x); a0.y = fmaf(v, s0.y, a0.y);
        a0.z = fmaf(v, s0.z, a0.z); a0.w = fmaf(v, s0.w, a0.w);
        a1.x = fmaf(v, s1.x, a1.x); a1.y = fmaf(v, s1.y, a1.y);
        a1.z = fmaf(v, s1.z, a1.z); a1.w = fmaf(v, s1.w, a1.w);
    }

    float4* po = reinterpret_cast<float4*>(out + (size_t)warp * D_OUT);
    po[lane]      = a0;
    po[lane + 32] = a1;
}

// ---------------------------------------------------------------------------
// Launch
// ---------------------------------------------------------------------------
extern "C" void kernel_launch(void* const* d_in, const int* in_sizes, int n_in,
                              void* d_out, int out_size)
{
    const float* x      = (const float*)d_in[0];
    const float* weight = (const float*)d_in[1];
    const int*   erow   = (const int*)  d_in[2];
    const int*   ecol   = (const int*)  d_in[3];
    const float* eval   = (const float*)d_in[4];
    float*       out    = (float*)d_out;

    float* support;
    cudaGetSymbolAddress((void**)&support, g_support);

    // CSR build
    zero_counts_kernel<<<(N_NODES + 255) / 256, 256>>>();
    count_kernel<<<(N_EDGES + 255) / 256, 256>>>(erow);
    scan_kernel<<<1, 1024>>>();
    scatter_kernel<<<(N_EDGES + 255) / 256, 256>>>(erow, ecol, eval);

    // bf16 hi/lo prep for both GEMM operands
    wprep_kernel<<<(D_IN * D_OUT + 255) / 256, 256>>>(weight);
    xprep_kernel<<<(N_NODES * D_IN / 4 + 255) / 256, 256>>>(x);

    // GEMM on tensor cores (mma.sync path)
    dim3 ggrid(2, (N_NODES + 127) / 128);      // n-blocks fast for L2 A-reuse
    gemm_mma_kernel<<<ggrid, 256>>>(support, N_NODES);

    // SpMM
    const int warps_per_block = 256 / 32;
    spmm_kernel<<<(N_NODES + warps_per_block - 1) / warps_per_block, 256>>>(support, out);
}

// round 8
// speedup vs baseline: 1.4394x; 1.4394x over previous
#include <cuda_runtime.h>
#include <cuda_bf16.h>
#include <stdint.h>

#define N_NODES  100000
#define N_EDGES  3200000
#define D_IN     256
#define D_OUT    256

// ---------------------------------------------------------------------------
// Device-global scratch
// ---------------------------------------------------------------------------
__device__ float          g_support[(size_t)N_NODES * D_OUT];   // ~102.4 MB
__device__ int            g_row_cnt[N_NODES];
__device__ int            g_row_off[N_NODES + 1];
__device__ int            g_row_cur[N_NODES];
__device__ int            g_csr_col[N_EDGES];
__device__ float          g_csr_val[N_EDGES];
__device__ __nv_bfloat16  g_wt_hi[D_IN * D_OUT];                // transposed [n][k]
__device__ __nv_bfloat16  g_wt_lo[D_IN * D_OUT];

// ---------------------------------------------------------------------------
// Helpers
// ---------------------------------------------------------------------------
__device__ __forceinline__ uint32_t smem_u32(const void* p) {
    uint32_t a;
    asm("{ .reg .u64 t; cvta.to.shared.u64 t, %1; cvt.u32.u64 %0, t; }"
        : "=r"(a) : "l"(p));
    return a;
}

// pack_bf16x2(a, b): lo half = bf16(a), hi half = bf16(b)
__device__ __forceinline__ uint32_t pack_bf16x2(float a, float b) {
    uint32_t r;
    asm("cvt.rn.satfinite.bf16x2.f32 %0, %1, %2;" : "=r"(r) : "f"(b), "f"(a));
    return r;
}

// mma.sync m16n8k16 row.col bf16 -> fp32 accumulate (sm_80 baseline, no 'a' gate)
__device__ __forceinline__ void mma_bf16(float* c, const uint32_t* a, const uint32_t* b) {
    asm volatile(
        "mma.sync.aligned.m16n8k16.row.col.f32.bf16.bf16.f32 "
        "{%0,%1,%2,%3}, {%4,%5,%6,%7}, {%8,%9}, {%0,%1,%2,%3};"
        : "+f"(c[0]), "+f"(c[1]), "+f"(c[2]), "+f"(c[3])
        : "r"(a[0]), "r"(a[1]), "r"(a[2]), "r"(a[3]), "r"(b[0]), "r"(b[1]));
}

__device__ __forceinline__ void ldsm_x4(uint32_t& r0, uint32_t& r1,
                                        uint32_t& r2, uint32_t& r3, uint32_t addr) {
    asm volatile("ldmatrix.sync.aligned.m8n8.x4.shared.b16 {%0,%1,%2,%3}, [%4];"
        : "=r"(r0), "=r"(r1), "=r"(r2), "=r"(r3) : "r"(addr));
}

// ---------------------------------------------------------------------------
// 0) Weight prep: Wt_hi[n][k] = bf16(W[k][n]),  Wt_lo = bf16(residual)
// ---------------------------------------------------------------------------
__global__ void wprep_kernel(const float* __restrict__ W)
{
    const int idx = blockIdx.x * blockDim.x + threadIdx.x;
    if (idx >= D_IN * D_OUT) return;
    const int k = idx / D_OUT;
    const int n = idx % D_OUT;
    const float v = W[idx];
    const __nv_bfloat16 hi = __float2bfloat16_rn(v);
    const float hif = __bfloat162float(hi);
    const __nv_bfloat16 lo = __float2bfloat16_rn(v - hif);
    g_wt_hi[n * D_IN + k] = hi;
    g_wt_lo[n * D_IN + k] = lo;
}

// ---------------------------------------------------------------------------
// 1) GEMM: support = x @ W, SMEM-staged mma.sync bf16 hi/lo (3 terms)
//    CTA 128x128, 8 warps (2m x 4n), warp tile 64x32.
//    SMEM pitch 144B (128B data + 16B pad) -> conflict-free STS & ldmatrix.
// ---------------------------------------------------------------------------
#define PITCHB 144                         // bytes per smem row (64 bf16 + 8 pad)
#define SM_AH  0
#define SM_AL  (128 * PITCHB)              // 18432
#define SM_BH  (2 * 128 * PITCHB)          // 36864
#define SM_BL  (3 * 128 * PITCHB)          // 55296
#define SM_GEMM_TOTAL (4 * 128 * PITCHB)   // 73728

__global__ __launch_bounds__(256, 2)
void gemm_mma_kernel(const float* __restrict__ X, float* __restrict__ S, int nrows)
{
    extern __shared__ char sm[];
    char* AH = sm + SM_AH;
    char* AL = sm + SM_AL;
    char* BH = sm + SM_BH;
    char* BL = sm + SM_BL;

    const int tid = threadIdx.x;
    const int w   = tid >> 5;
    const int l   = tid & 31;
    const int mblock = blockIdx.y * 128;
    const int nblock = blockIdx.x * 128;   // gridDim.x == 2
    const int wm = (w & 1) * 64;
    const int wn = (w >> 1) * 32;

    // Global-load mappings
    const int a_c4 = tid & 15;             // float4 col within 64-k slice
    const int a_rg = tid >> 4;             // 0..15
    const int b_ch = tid & 7;              // 16B chunk within 128B k-row
    const int b_rg = tid >> 3;             // 0..31

    float acc[4][4][4];
    #pragma unroll
    for (int mf = 0; mf < 4; mf++)
        #pragma unroll
        for (int nf = 0; nf < 4; nf++)
            #pragma unroll
            for (int r = 0; r < 4; r++) acc[mf][nf][r] = 0.0f;

    for (int s = 0; s < 4; s++) {          // 4 k-slices of 64
        const int k0 = s * 64;

        // --- A: 128 rows x 64 k fp32 -> bf16 hi/lo into smem
        #pragma unroll
        for (int i = 0; i < 8; i++) {
            const int r  = a_rg + 16 * i;
            const int gr = mblock + r;
            uint32_t h01 = 0, h23 = 0, l01 = 0, l23 = 0;
            if (gr < nrows) {
                const float4 v = *reinterpret_cast<const float4*>(
                    X + (size_t)gr * D_IN + k0 + a_c4 * 4);
                h01 = pack_bf16x2(v.x, v.y);
                h23 = pack_bf16x2(v.z, v.w);
                const float f0 = __uint_as_float(h01 << 16);
                const float f1 = __uint_as_float(h01 & 0xffff0000u);
                const float f2 = __uint_as_float(h23 << 16);
                const float f3 = __uint_as_float(h23 & 0xffff0000u);
                l01 = pack_bf16x2(v.x - f0, v.y - f1);
                l23 = pack_bf16x2(v.z - f2, v.w - f3);
            }
            *reinterpret_cast<uint2*>(AH + r * PITCHB + a_c4 * 8) = make_uint2(h01, h23);
            *reinterpret_cast<uint2*>(AL + r * PITCHB + a_c4 * 8) = make_uint2(l01, l23);
        }

        // --- B: 128 n-rows x 64 k bf16 from g_wt (k-contig)
        #pragma unroll
        for (int i = 0; i < 4; i++) {
            const int n = b_rg + 32 * i;
            const size_t off = ((size_t)(nblock + n) * D_IN + k0) * 2 + b_ch * 16;
            const uint4 vh = *reinterpret_cast<const uint4*>(
                reinterpret_cast<const char*>(g_wt_hi) + off);
            const uint4 vl = *reinterpret_cast<const uint4*>(
                reinterpret_cast<const char*>(g_wt_lo) + off);
            *reinterpret_cast<uint4*>(BH + n * PITCHB + b_ch * 16) = vh;
            *reinterpret_cast<uint4*>(BL + n * PITCHB + b_ch * 16) = vl;
        }
        __syncthreads();

        #pragma unroll
        for (int kk = 0; kk < 4; kk++) {   // 4 k-steps of 16
            const int kb = kk * 32;        // byte offset of k-step

            // B fragments: one x4 covers two nf (b0,b1 each)
            uint32_t bh[4][2], bl[4][2];
            #pragma unroll
            for (int pf = 0; pf < 2; pf++) {
                const int nrow  = wn + pf * 16 + ((l >> 4) << 3) + (l & 7);
                const int kbyte = kb + ((l >> 3) & 1) * 16;
                const uint32_t ah_ = smem_u32(BH + nrow * PITCHB + kbyte);
                const uint32_t al_ = smem_u32(BL + nrow * PITCHB + kbyte);
                ldsm_x4(bh[2*pf][0], bh[2*pf][1], bh[2*pf+1][0], bh[2*pf+1][1], ah_);
                ldsm_x4(bl[2*pf][0], bl[2*pf][1], bl[2*pf+1][0], bl[2*pf+1][1], al_);
            }

            #pragma unroll
            for (int mf = 0; mf < 4; mf++) {
                const int arow  = wm + mf * 16 + ((l >> 3) & 1) * 8 + (l & 7);
                const int kbyte = kb + (l >> 4) * 16;
                uint32_t a_h[4], a_l[4];
                ldsm_x4(a_h[0], a_h[1], a_h[2], a_h[3],
                        smem_u32(AH + arow * PITCHB + kbyte));
                ldsm_x4(a_l[0], a_l[1], a_l[2], a_l[3],
                        smem_u32(AL + arow * PITCHB + kbyte));
                #pragma unroll
                for (int nf = 0; nf < 4; nf++) {
                    mma_bf16(acc[mf][nf], a_h, bh[nf]);
                    mma_bf16(acc[mf][nf], a_h, bl[nf]);
                    mma_bf16(acc[mf][nf], a_l, bh[nf]);
                }
            }
        }
        __syncthreads();
    }

    // Epilogue: c0,c1 -> (row, col..col+1); c2,c3 -> (row+8, ...)
    const int lr = l >> 2;
    const int lq = l & 3;
    #pragma unroll
    for (int mf = 0; mf < 4; mf++) {
        const int r0 = mblock + wm + mf * 16 + lr;
        const int r1 = r0 + 8;
        #pragma unroll
        for (int nf = 0; nf < 4; nf++) {
            const int col = nblock + wn + nf * 8 + lq * 2;
            if (r0 < nrows)
                *reinterpret_cast<float2*>(S + (size_t)r0 * D_OUT + col) =
                    make_float2(acc[mf][nf][0], acc[mf][nf][1]);
            if (r1 < nrows)
                *reinterpret_cast<float2*>(S + (size_t)r1 * D_OUT + col) =
                    make_float2(acc[mf][nf][2], acc[mf][nf][3]);
        }
    }
}

// ---------------------------------------------------------------------------
// 2) CSR build
// ---------------------------------------------------------------------------
__global__ void zero_counts_kernel()
{
    const int i = blockIdx.x * blockDim.x + threadIdx.x;
    if (i < N_NODES) g_row_cnt[i] = 0;
}

__global__ void count_kernel(const int* __restrict__ erow)
{
    const int e = blockIdx.x * blockDim.x + threadIdx.x;
    if (e < N_EDGES) atomicAdd(&g_row_cnt[erow[e]], 1);
}

__global__ void scan_kernel()
{
    const int T = 1024;
    const int t = threadIdx.x;
    const int chunk = (N_NODES + T - 1) / T;
    const int start = t * chunk;
    const int end   = min(start + chunk, N_NODES);

    int sum = 0;
    for (int i = start; i < end; i++) sum += g_row_cnt[i];

    __shared__ int s[T];
    s[t] = sum;
    __syncthreads();
    for (int d = 1; d < T; d <<= 1) {
        int v = (t >= d) ? s[t - d] : 0;
        __syncthreads();
        s[t] += v;
        __syncthreads();
    }
    int run = s[t] - sum;
    for (int i = start; i < end; i++) {
        const int c = g_row_cnt[i];
        g_row_off[i] = run;
        g_row_cur[i] = run;
        run += c;
    }
    if (end == N_NODES) g_row_off[N_NODES] = run;
}

__global__ void scatter_kernel(const int* __restrict__ erow,
                               const int* __restrict__ ecol,
                               const float* __restrict__ eval)
{
    const int e = blockIdx.x * blockDim.x + threadIdx.x;
    if (e < N_EDGES) {
        const int r   = erow[e];
        const int pos = atomicAdd(&g_row_cur[r], 1);
        g_csr_col[pos] = ecol[e];
        g_csr_val[pos] = eval[e];
    }
}

// ---------------------------------------------------------------------------
// 3) SpMM: warp-per-row, 2-edge software pipeline
// ---------------------------------------------------------------------------
__global__ __launch_bounds__(256)
void spmm_kernel(const float* __restrict__ S, float* __restrict__ out)
{
    const int warp = blockIdx.x * (blockDim.x >> 5) + (threadIdx.x >> 5);
    const int lane = threadIdx.x & 31;
    if (warp >= N_NODES) return;

    const int beg = g_row_off[warp];
    const int end = g_row_off[warp + 1];

    float4 a0 = make_float4(0.f, 0.f, 0.f, 0.f);
    float4 a1 = make_float4(0.f, 0.f, 0.f, 0.f);

    int e = beg;
    for (; e + 2 <= end; e += 2) {
        const int   c0 = __ldg(&g_csr_col[e]);
        const int   c1 = __ldg(&g_csr_col[e + 1]);
        const float v0 = __ldg(&g_csr_val[e]);
        const float v1 = __ldg(&g_csr_val[e + 1]);
        const float4* p0 = reinterpret_cast<const float4*>(S + (size_t)c0 * D_OUT);
        const float4* p1 = reinterpret_cast<const float4*>(S + (size_t)c1 * D_OUT);
        const float4 x0 = __ldg(p0 + lane);
        const float4 x1 = __ldg(p0 + lane + 32);
        const float4 y0 = __ldg(p1 + lane);
        const float4 y1 = __ldg(p1 + lane + 32);
        a0.x = fmaf(v0, x0.x, a0.x); a0.y = fmaf(v0, x0.y, a0.y);
        a0.z = fmaf(v0, x0.z, a0.z); a0.w = fmaf(v0, x0.w, a0.w);
        a1.x = fmaf(v0, x1.x, a1.x); a1.y = fmaf(v0, x1.y, a1.y);
        a1.z = fmaf(v0, x1.z, a1.z); a1.w = fmaf(v0, x1.w, a1.w);
        a0.x = fmaf(v1, y0.x, a0.x); a0.y = fmaf(v1, y0.y, a0.y);
        a0.z = fmaf(v1, y0.z, a0.z); a0.w = fmaf(v1, y0.w, a0.w);
        a1.x = fmaf(v1, y1.x, a1.x); a1.y = fmaf(v1, y1.y, a1.y);
        a1.z = fmaf(v1, y1.z, a1.z); a1.w = fmaf(v1, y1.w, a1.w);
    }
    for (; e < end; e++) {
        const int   c = __ldg(&g_csr_col[e]);
        const float v = __ldg(&g_csr_val[e]);
        const float4* p = reinterpret_cast<const float4*>(S + (size_t)c * D_OUT);
        const float4 s0 = __ldg(p + lane);
        const float4 s1 = __ldg(p + lane + 32);
        a0.x = fmaf(v, s0.x, a0.x); a0.y = fmaf(v, s0.y, a0.y);
        a0.z = fmaf(v, s0.z, a0.z); a0.w = fmaf(v, s0.w, a0.w);
        a1.x = fmaf(v, s1.x, a1.x); a1.y = fmaf(v, s1.y, a1.y);
        a1.z = fmaf(v, s1.z, a1.z); a1.w = fmaf(v, s1.w, a1.w);
    }

    float4* po = reinterpret_cast<float4*>(out + (size_t)warp * D_OUT);
    po[lane]      = a0;
    po[lane + 32] = a1;
}

// ---------------------------------------------------------------------------
// Launch
// ---------------------------------------------------------------------------
extern "C" void kernel_launch(void* const* d_in, const int* in_sizes, int n_in,
                              void* d_out, int out_size)
{
    const float* x      = (const float*)d_in[0];
    const float* weight = (const float*)d_in[1];
    const int*   erow   = (const int*)  d_in[2];
    const int*   ecol   = (const int*)  d_in[3];
    const float* eval   = (const float*)d_in[4];
    float*       out    = (float*)d_out;

    float* support;
    cudaGetSymbolAddress((void**)&support, g_support);

    // Unconditional, idempotent, enqueues no work (capture-legal).
    cudaFuncSetAttribute(gemm_mma_kernel,
                         cudaFuncAttributeMaxDynamicSharedMemorySize, SM_GEMM_TOTAL);

    // CSR build
    zero_counts_kernel<<<(N_NODES + 255) / 256, 256>>>();
    count_kernel<<<(N_EDGES + 255) / 256, 256>>>(erow);
    scan_kernel<<<1, 1024>>>();
    scatter_kernel<<<(N_EDGES + 255) / 256, 256>>>(erow, ecol, eval);

    // Weight split + transpose (bf16 hi/lo)
    wprep_kernel<<<(D_IN * D_OUT + 255) / 256, 256>>>(weight);

    // GEMM on tensor cores (smem-staged mma.sync)
    dim3 ggrid(2, (N_NODES + 127) / 128);      // n-blocks fast for L2 A-reuse
    gemm_mma_kernel<<<ggrid, 256, SM_GEMM_TOTAL>>>(x, support, N_NODES);

    // SpMM
    const int warps_per_block = 256 / 32;
    spmm_kernel<<<(N_NODES + warps_per_block - 1) / warps_per_block, 256>>>(support, out);
}

// round 10
// speedup vs baseline: 2.3700x; 1.6466x over previous
#include <cuda_runtime.h>
#include <cuda_bf16.h>
#include <cuda_fp16.h>
#include <stdint.h>

#define N_NODES  100000
#define N_EDGES  3200000
#define D_IN     256
#define D_OUT    256

// ---------------------------------------------------------------------------
// Device-global scratch
// ---------------------------------------------------------------------------
__device__ __half         g_support[(size_t)N_NODES * D_OUT];   // ~51.2 MB (fp16)
__device__ int            g_row_cnt[N_NODES];
__device__ int            g_row_off[N_NODES + 1];
__device__ int            g_row_cur[N_NODES];
__device__ int            g_csr_col[N_EDGES];
__device__ float          g_csr_val[N_EDGES];
__device__ __nv_bfloat16  g_wt_hi[D_IN * D_OUT];                // transposed [n][k]
__device__ __nv_bfloat16  g_wt_lo[D_IN * D_OUT];

// ---------------------------------------------------------------------------
// Static host resources for stream-fork graph capture (created pre-main;
// no per-call guards, no device memory allocation).
// ---------------------------------------------------------------------------
static cudaStream_t g_s2;
static cudaEvent_t  g_ev_fork, g_ev_join;
namespace {
struct HostInit {
    HostInit() {
        cudaStreamCreateWithFlags(&g_s2, cudaStreamNonBlocking);
        cudaEventCreateWithFlags(&g_ev_fork, cudaEventDisableTiming);
        cudaEventCreateWithFlags(&g_ev_join, cudaEventDisableTiming);
    }
};
static HostInit g_host_init;
}

// ---------------------------------------------------------------------------
// Helpers
// ---------------------------------------------------------------------------
__device__ __forceinline__ uint32_t smem_u32(const void* p) {
    uint32_t a;
    asm("{ .reg .u64 t; cvta.to.shared.u64 t, %1; cvt.u32.u64 %0, t; }"
        : "=r"(a) : "l"(p));
    return a;
}

// pack_bf16x2(a, b): lo half = bf16(a), hi half = bf16(b)
__device__ __forceinline__ uint32_t pack_bf16x2(float a, float b) {
    uint32_t r;
    asm("cvt.rn.satfinite.bf16x2.f32 %0, %1, %2;" : "=r"(r) : "f"(b), "f"(a));
    return r;
}

// mma.sync m16n8k16 row.col bf16 -> fp32 accumulate (sm_80 baseline, no 'a' gate)
__device__ __forceinline__ void mma_bf16(float* c, const uint32_t* a, const uint32_t* b) {
    asm volatile(
        "mma.sync.aligned.m16n8k16.row.col.f32.bf16.bf16.f32 "
        "{%0,%1,%2,%3}, {%4,%5,%6,%7}, {%8,%9}, {%0,%1,%2,%3};"
        : "+f"(c[0]), "+f"(c[1]), "+f"(c[2]), "+f"(c[3])
        : "r"(a[0]), "r"(a[1]), "r"(a[2]), "r"(a[3]), "r"(b[0]), "r"(b[1]));
}

__device__ __forceinline__ void ldsm_x4(uint32_t& r0, uint32_t& r1,
                                        uint32_t& r2, uint32_t& r3, uint32_t addr) {
    asm volatile("ldmatrix.sync.aligned.m8n8.x4.shared.b16 {%0,%1,%2,%3}, [%4];"
        : "=r"(r0), "=r"(r1), "=r"(r2), "=r"(r3) : "r"(addr));
}

// ---------------------------------------------------------------------------
// 0) Weight prep: Wt_hi[n][k] = bf16(W[k][n]),  Wt_lo = bf16(residual)
// ---------------------------------------------------------------------------
__global__ void wprep_kernel(const float* __restrict__ W)
{
    const int idx = blockIdx.x * blockDim.x + threadIdx.x;
    if (idx >= D_IN * D_OUT) return;
    const int k = idx / D_OUT;
    const int n = idx % D_OUT;
    const float v = W[idx];
    const __nv_bfloat16 hi = __float2bfloat16_rn(v);
    const float hif = __bfloat162float(hi);
    const __nv_bfloat16 lo = __float2bfloat16_rn(v - hif);
    g_wt_hi[n * D_IN + k] = hi;
    g_wt_lo[n * D_IN + k] = lo;
}

// ---------------------------------------------------------------------------
// 1) GEMM: support = x @ W, SMEM-staged mma.sync bf16 hi/lo (3 terms)
//    CTA 128x128, 8 warps (2m x 4n), warp tile 64x32. Output stored fp16.
// ---------------------------------------------------------------------------
#define PITCHB 144                         // bytes per smem row (64 bf16 + 8 pad)
#define SM_AH  0
#define SM_AL  (128 * PITCHB)
#define SM_BH  (2 * 128 * PITCHB)
#define SM_BL  (3 * 128 * PITCHB)
#define SM_GEMM_TOTAL (4 * 128 * PITCHB)   // 73728

__global__ __launch_bounds__(256, 2)
void gemm_mma_kernel(const float* __restrict__ X, __half* __restrict__ S, int nrows)
{
    extern __shared__ char sm[];
    char* AH = sm + SM_AH;
    char* AL = sm + SM_AL;
    char* BH = sm + SM_BH;
    char* BL = sm + SM_BL;

    const int tid = threadIdx.x;
    const int w   = tid >> 5;
    const int l   = tid & 31;
    const int mblock = blockIdx.y * 128;
    const int nblock = blockIdx.x * 128;   // gridDim.x == 2
    const int wm = (w & 1) * 64;
    const int wn = (w >> 1) * 32;

    const int a_c4 = tid & 15;
    const int a_rg = tid >> 4;
    const int b_ch = tid & 7;
    const int b_rg = tid >> 3;

    float acc[4][4][4];
    #pragma unroll
    for (int mf = 0; mf < 4; mf++)
        #pragma unroll
        for (int nf = 0; nf < 4; nf++)
            #pragma unroll
            for (int r = 0; r < 4; r++) acc[mf][nf][r] = 0.0f;

    for (int s = 0; s < 4; s++) {          // 4 k-slices of 64
        const int k0 = s * 64;

        #pragma unroll
        for (int i = 0; i < 8; i++) {
            const int r  = a_rg + 16 * i;
            const int gr = mblock + r;
            uint32_t h01 = 0, h23 = 0, l01 = 0, l23 = 0;
            if (gr < nrows) {
                const float4 v = *reinterpret_cast<const float4*>(
                    X + (size_t)gr * D_IN + k0 + a_c4 * 4);
                h01 = pack_bf16x2(v.x, v.y);
                h23 = pack_bf16x2(v.z, v.w);
                const float f0 = __uint_as_float(h01 << 16);
                const float f1 = __uint_as_float(h01 & 0xffff0000u);
                const float f2 = __uint_as_float(h23 << 16);
                const float f3 = __uint_as_float(h23 & 0xffff0000u);
                l01 = pack_bf16x2(v.x - f0, v.y - f1);
                l23 = pack_bf16x2(v.z - f2, v.w - f3);
            }
            *reinterpret_cast<uint2*>(AH + r * PITCHB + a_c4 * 8) = make_uint2(h01, h23);
            *reinterpret_cast<uint2*>(AL + r * PITCHB + a_c4 * 8) = make_uint2(l01, l23);
        }

        #pragma unroll
        for (int i = 0; i < 4; i++) {
            const int n = b_rg + 32 * i;
            const size_t off = ((size_t)(nblock + n) * D_IN + k0) * 2 + b_ch * 16;
            const uint4 vh = *reinterpret_cast<const uint4*>(
                reinterpret_cast<const char*>(g_wt_hi) + off);
            const uint4 vl = *reinterpret_cast<const uint4*>(
                reinterpret_cast<const char*>(g_wt_lo) + off);
            *reinterpret_cast<uint4*>(BH + n * PITCHB + b_ch * 16) = vh;
            *reinterpret_cast<uint4*>(BL + n * PITCHB + b_ch * 16) = vl;
        }
        __syncthreads();

        #pragma unroll
        for (int kk = 0; kk < 4; kk++) {   // 4 k-steps of 16
            const int kb = kk * 32;

            uint32_t bh[4][2], bl[4][2];
            #pragma unroll
            for (int pf = 0; pf < 2; pf++) {
                const int nrow  = wn + pf * 16 + ((l >> 4) << 3) + (l & 7);
                const int kbyte = kb + ((l >> 3) & 1) * 16;
                const uint32_t ah_ = smem_u32(BH + nrow * PITCHB + kbyte);
                const uint32_t al_ = smem_u32(BL + nrow * PITCHB + kbyte);
                ldsm_x4(bh[2*pf][0], bh[2*pf][1], bh[2*pf+1][0], bh[2*pf+1][1], ah_);
                ldsm_x4(bl[2*pf][0], bl[2*pf][1], bl[2*pf+1][0], bl[2*pf+1][1], al_);
            }

            #pragma unroll
            for (int mf = 0; mf < 4; mf++) {
                const int arow  = wm + mf * 16 + ((l >> 3) & 1) * 8 + (l & 7);
                const int kbyte = kb + (l >> 4) * 16;
                uint32_t a_h[4], a_l[4];
                ldsm_x4(a_h[0], a_h[1], a_h[2], a_h[3],
                        smem_u32(AH + arow * PITCHB + kbyte));
                ldsm_x4(a_l[0], a_l[1], a_l[2], a_l[3],
                        smem_u32(AL + arow * PITCHB + kbyte));
                #pragma unroll
                for (int nf = 0; nf < 4; nf++) {
                    mma_bf16(acc[mf][nf], a_h, bh[nf]);
                    mma_bf16(acc[mf][nf], a_h, bl[nf]);
                    mma_bf16(acc[mf][nf], a_l, bh[nf]);
                }
            }
        }
        __syncthreads();
    }

    // Epilogue -> fp16 support. c0,c1 -> (row, col..col+1); c2,c3 -> (row+8, ...)
    const int lr = l >> 2;
    const int lq = l & 3;
    #pragma unroll
    for (int mf = 0; mf < 4; mf++) {
        const int r0 = mblock + wm + mf * 16 + lr;
        const int r1 = r0 + 8;
        #pragma unroll
        for (int nf = 0; nf < 4; nf++) {
            const int col = nblock + wn + nf * 8 + lq * 2;
            if (r0 < nrows)
                *reinterpret_cast<__half2*>(S + (size_t)r0 * D_OUT + col) =
                    __floats2half2_rn(acc[mf][nf][0], acc[mf][nf][1]);
            if (r1 < nrows)
                *reinterpret_cast<__half2*>(S + (size_t)r1 * D_OUT + col) =
                    __floats2half2_rn(acc[mf][nf][2], acc[mf][nf][3]);
        }
    }
}

// ---------------------------------------------------------------------------
// 2) CSR build
// ---------------------------------------------------------------------------
__global__ void zero_counts_kernel()
{
    const int i = blockIdx.x * blockDim.x + threadIdx.x;
    if (i < N_NODES) g_row_cnt[i] = 0;
}

__global__ void count_kernel(const int* __restrict__ erow)
{
    const int e = blockIdx.x * blockDim.x + threadIdx.x;
    if (e < N_EDGES) atomicAdd(&g_row_cnt[erow[e]], 1);
}

__global__ void scan_kernel()
{
    const int T = 1024;
    const int t = threadIdx.x;
    const int chunk = (N_NODES + T - 1) / T;
    const int start = t * chunk;
    const int end   = min(start + chunk, N_NODES);

    int sum = 0;
    for (int i = start; i < end; i++) sum += g_row_cnt[i];

    __shared__ int s[T];
    s[t] = sum;
    __syncthreads();
    for (int d = 1; d < T; d <<= 1) {
        int v = (t >= d) ? s[t - d] : 0;
        __syncthreads();
        s[t] += v;
        __syncthreads();
    }
    int run = s[t] - sum;
    for (int i = start; i < end; i++) {
        const int c = g_row_cnt[i];
        g_row_off[i] = run;
        g_row_cur[i] = run;
        run += c;
    }
    if (end == N_NODES) g_row_off[N_NODES] = run;
}

__global__ void scatter_kernel(const int* __restrict__ erow,
                               const int* __restrict__ ecol,
                               const float* __restrict__ eval)
{
    const int e = blockIdx.x * blockDim.x + threadIdx.x;
    if (e < N_EDGES) {
        const int r   = erow[e];
        const int pos = atomicAdd(&g_row_cur[r], 1);
        g_csr_col[pos] = ecol[e];
        g_csr_val[pos] = eval[e];
    }
}

// ---------------------------------------------------------------------------
// 3) SpMM: warp-per-row over fp16 support, fp32 accumulate.
//    Per edge: each lane reads one uint4 (8 halves = 8 cols). 2-edge pipeline.
// ---------------------------------------------------------------------------
__global__ __launch_bounds__(256)
void spmm_kernel(const __half* __restrict__ S, float* __restrict__ out)
{
    const int warp = blockIdx.x * (blockDim.x >> 5) + (threadIdx.x >> 5);
    const int lane = threadIdx.x & 31;
    if (warp >= N_NODES) return;

    const int beg = g_row_off[warp];
    const int end = g_row_off[warp + 1];

    float2 a[4];
    #pragma unroll
    for (int j = 0; j < 4; j++) a[j] = make_float2(0.f, 0.f);

    int e = beg;
    for (; e + 2 <= end; e += 2) {
        const int   c0 = __ldg(&g_csr_col[e]);
        const int   c1 = __ldg(&g_csr_col[e + 1]);
        const float v0 = __ldg(&g_csr_val[e]);
        const float v1 = __ldg(&g_csr_val[e + 1]);
        const uint4 q0 = __ldg(reinterpret_cast<const uint4*>(S + (size_t)c0 * D_OUT) + lane);
        const uint4 q1 = __ldg(reinterpret_cast<const uint4*>(S + (size_t)c1 * D_OUT) + lane);
        const __half2* h0 = reinterpret_cast<const __half2*>(&q0);
        const __half2* h1 = reinterpret_cast<const __half2*>(&q1);
        #pragma unroll
        for (int j = 0; j < 4; j++) {
            const float2 f0 = __half22float2(h0[j]);
            const float2 f1 = __half22float2(h1[j]);
            a[j].x = fmaf(v0, f0.x, a[j].x);
            a[j].y = fmaf(v0, f0.y, a[j].y);
            a[j].x = fmaf(v1, f1.x, a[j].x);
            a[j].y = fmaf(v1, f1.y, a[j].y);
        }
    }
    for (; e < end; e++) {
        const int   c = __ldg(&g_csr_col[e]);
        const float v = __ldg(&g_csr_val[e]);
        const uint4 q = __ldg(reinterpret_cast<const uint4*>(S + (size_t)c * D_OUT) + lane);
        const __half2* h = reinterpret_cast<const __half2*>(&q);
        #pragma unroll
        for (int j = 0; j < 4; j++) {
            const float2 f = __half22float2(h[j]);
            a[j].x = fmaf(v, f.x, a[j].x);
            a[j].y = fmaf(v, f.y, a[j].y);
        }
    }

    // Each lane owns cols [lane*8, lane*8+8)
    float4* po = reinterpret_cast<float4*>(out + (size_t)warp * D_OUT + lane * 8);
    po[0] = make_float4(a[0].x, a[0].y, a[1].x, a[1].y);
    po[1] = make_float4(a[2].x, a[2].y, a[3].x, a[3].y);
}

// ---------------------------------------------------------------------------
// Launch: fork CSR chain onto g_s2, run wprep+GEMM on the capture stream,
// join before SpMM. Identical call sequence every invocation.
// ---------------------------------------------------------------------------
extern "C" void kernel_launch(void* const* d_in, const int* in_sizes, int n_in,
                              void* d_out, int out_size)
{
    const float* x      = (const float*)d_in[0];
    const float* weight = (const float*)d_in[1];
    const int*   erow   = (const int*)  d_in[2];
    const int*   ecol   = (const int*)  d_in[3];
    const float* eval   = (const float*)d_in[4];
    float*       out    = (float*)d_out;

    __half* support;
    cudaGetSymbolAddress((void**)&support, g_support);

    cudaFuncSetAttribute(gemm_mma_kernel,
                         cudaFuncAttributeMaxDynamicSharedMemorySize, SM_GEMM_TOTAL);

    // Fork: CSR chain on g_s2
    cudaEventRecord(g_ev_fork, 0);
    cudaStreamWaitEvent(g_s2, g_ev_fork, 0);

    zero_counts_kernel<<<(N_NODES + 255) / 256, 256, 0, g_s2>>>();
    count_kernel<<<(N_EDGES + 255) / 256, 256, 0, g_s2>>>(erow);
    scan_kernel<<<1, 1024, 0, g_s2>>>();
    scatter_kernel<<<(N_EDGES + 255) / 256, 256, 0, g_s2>>>(erow, ecol, eval);

    // Main stream: weight prep + GEMM (independent of edges)
    wprep_kernel<<<(D_IN * D_OUT + 255) / 256, 256>>>(weight);
    dim3 ggrid(2, (N_NODES + 127) / 128);
    gemm_mma_kernel<<<ggrid, 256, SM_GEMM_TOTAL>>>(x, support, N_NODES);

    // Join: SpMM needs both branches
    cudaEventRecord(g_ev_join, g_s2);
    cudaStreamWaitEvent(0, g_ev_join, 0);

    const int warps_per_block = 256 / 32;
    spmm_kernel<<<(N_NODES + warps_per_block - 1) / warps_per_block, 256>>>(support, out);
}